// round 1
// baseline (speedup 1.0000x reference)
#include <cuda_runtime.h>

#define NN   50000
#define C    128
#define E    800000
#define EF   65
#define EAC  70
#define ET   32

// ---------------- scratch (device globals; no allocation allowed) ------------
__device__ float g_A [C*C];           // Wf1 + Wf3
__device__ float g_B [C*C];           // Wf2 - Wf3
__device__ float g_M [C*C];           // scale * Wq diag(Wa) Wk^T
__device__ float g_XA[NN*C];          // x @ A
__device__ float g_XB[NN*C];          // x @ B
__device__ float g_Xm[NN*C];          // x @ M
__device__ float g_f [(size_t)E*C];   // per-edge f rows (409.6 MB)
__device__ float g_a [E];             // per-edge attention scalar
__device__ float g_asum[NN];          // segment sum of a over src
__device__ float g_aggr[NN*C];        // segment sum of z over src

// ---------------- packed fp32x2 helpers (Blackwell FFMA2) --------------------
__device__ __forceinline__ void fma2(unsigned long long &acc,
                                     unsigned long long a, unsigned long long b) {
    asm("fma.rn.f32x2 %0, %1, %2, %0;" : "+l"(acc) : "l"(a), "l"(b));
}
__device__ __forceinline__ unsigned long long dup2(float v) {
    unsigned int u = __float_as_uint(v);
    return ((unsigned long long)u << 32) | (unsigned long long)u;
}
__device__ __forceinline__ unsigned long long pack2(float x, float y) {
    return ((unsigned long long)__float_as_uint(y) << 32)
         |  (unsigned long long)__float_as_uint(x);
}
__device__ __forceinline__ float2 unpack2(unsigned long long p) {
    float2 r;
    r.x = __uint_as_float((unsigned int)(p & 0xffffffffull));
    r.y = __uint_as_float((unsigned int)(p >> 32));
    return r;
}

// ---------------- K0: fold weights ------------------------------------------
// A = Wf[0:128]+Wf[256:384], B = Wf[128:256]-Wf[256:384],
// M[d][j] = scale * sum_c Wq[d][c]*Wa[c]*Wk[j][c]
__global__ void prep_kernel(const float* __restrict__ Wf, const float* __restrict__ Wq,
                            const float* __restrict__ Wk, const float* __restrict__ Wa) {
    int d = blockIdx.x;      // 0..127
    int c = threadIdx.x;     // 0..127
    g_A[d*C + c] = Wf[d*C + c]        + Wf[(256+d)*C + c];
    g_B[d*C + c] = Wf[(128+d)*C + c]  - Wf[(256+d)*C + c];
    __shared__ float sWa[C], sWq[C];
    sWa[c] = Wa[c];
    sWq[c] = Wq[d*C + c];
    __syncthreads();
    float acc = 0.0f;
    #pragma unroll 4
    for (int k = 0; k < C; k++) acc += sWq[k] * sWa[k] * Wk[c*C + k];
    g_M[d*C + c] = acc * 0.08838834764831845f;   // 128^-0.5
}

// ---------------- zero the accumulators (graph-safe, no memset symbols) -----
__global__ void zero_kernel() {
    int i = blockIdx.x * blockDim.x + threadIdx.x;
    if (i < NN*C) g_aggr[i] = 0.0f;
    if (i < NN)   g_asum[i] = 0.0f;
}

// ---------------- K1: node precompute XA, XB, Xm -----------------------------
// block = 128 thr (4 warps), 32 nodes/tile; each warp: 8 nodes, all 128 ch
// (2 f32x2 pairs per lane). Weights staged in smem once per matrix per block.
__global__ __launch_bounds__(128) void node_pre_kernel(const float* __restrict__ x) {
    extern __shared__ unsigned char smem[];
    float2* sW2 = (float2*)smem;                                     // [128][64]
    unsigned long long* sX2 = (unsigned long long*)(smem + 65536);   // [128][33]
    int tid = threadIdx.x, lane = tid & 31, w = tid >> 5;
    const float* Ws[3] = {g_A, g_B, g_M};
    float*       Ys[3] = {g_XA, g_XB, g_Xm};
    const int ntiles = (NN + 31) / 32;
    for (int m = 0; m < 3; m++) {
        __syncthreads();
        const float2* W2 = (const float2*)Ws[m];
        for (int i = tid; i < C*64; i += 128) sW2[i] = W2[i];
        float* Y = Ys[m];
        for (int tile = blockIdx.x; tile < ntiles; tile += gridDim.x) {
            int n0 = tile * 32;
            __syncthreads();
            for (int i = tid; i < C*32; i += 128) {
                int d = i & 127, n = i >> 7, ng = n0 + n;
                float v = (ng < NN) ? x[ng*C + d] : 0.0f;
                sX2[d*33 + n] = dup2(v);
            }
            __syncthreads();
            int nb = w * 8;
            unsigned long long a0[8], a1[8];
            #pragma unroll
            for (int e = 0; e < 8; e++) { a0[e] = 0ull; a1[e] = 0ull; }
            #pragma unroll 4
            for (int d = 0; d < C; d++) {
                unsigned long long w0 = *(const unsigned long long*)(sW2 + d*64 + lane);
                unsigned long long w1 = *(const unsigned long long*)(sW2 + d*64 + lane + 32);
                #pragma unroll
                for (int e = 0; e < 8; e++) {
                    unsigned long long xv = sX2[d*33 + nb + e];
                    fma2(a0[e], xv, w0);
                    fma2(a1[e], xv, w1);
                }
            }
            #pragma unroll 1
            for (int e = 0; e < 8; e++) {
                int n = n0 + nb + e;
                if (n < NN) {
                    *(float2*)(Y + n*C + 2*lane)      = unpack2(a0[e]);
                    *(float2*)(Y + n*C + 2*lane + 64) = unpack2(a1[e]);
                }
            }
        }
    }
}

// ---------------- K2: edge pass 1 — f, a, a_sum ------------------------------
// block = 128 thr (4 warps), 32 edges/tile, each warp 8 edges × 128 channels.
// f = elu(XA[src] + XB[tgt] + ea@W4 + bf) * mask ; a = tanh(Xm[src]·f)
__global__ __launch_bounds__(128) void edge1_kernel(const float* __restrict__ ea,
                                                    const int*   __restrict__ ei,
                                                    const float* __restrict__ Wf,
                                                    const float* __restrict__ bf) {
    extern __shared__ unsigned char smem[];
    float2*             sW4  = (float2*)smem;                                 // [65][64]  33280B
    unsigned long long* sEa2 = (unsigned long long*)(smem + 33280);           // [65][32]  16640B
    float2*             sBf2 = (float2*)(smem + 49920);                       // [64]        512B
    int*                sIdx = (int*)(smem + 50432);                          // [64]        256B
    int tid = threadIdx.x, lane = tid & 31, w = tid >> 5;

    for (int i = tid; i < EF*64; i += 128) {
        int d = i >> 6, p = i & 63;
        sW4[i] = *(const float2*)(Wf + (3*C + d)*C + 2*p);
    }
    if (tid < 64) sBf2[tid] = *(const float2*)(bf + 2*tid);

    const int ntiles = E / ET;   // 25000
    for (int tile = blockIdx.x; tile < ntiles; tile += gridDim.x) {
        int e0 = tile * ET;
        __syncthreads();
        if (tid < ET) { sIdx[tid] = ei[e0 + tid]; sIdx[ET + tid] = ei[E + e0 + tid]; }
        for (int i = tid; i < EF*ET; i += 128) {
            int e = i & 31, d = i >> 5;
            sEa2[d*ET + e] = dup2(ea[(size_t)(e0 + e)*EAC + d]);
        }
        __syncthreads();

        int eb = w * 8;
        unsigned long long a0[8], a1[8];
        {
            unsigned long long b0 = *(const unsigned long long*)(sBf2 + lane);
            unsigned long long b1 = *(const unsigned long long*)(sBf2 + lane + 32);
            #pragma unroll
            for (int e = 0; e < 8; e++) { a0[e] = b0; a1[e] = b1; }
        }
        #pragma unroll 5
        for (int d = 0; d < EF; d++) {
            unsigned long long w0 = *(const unsigned long long*)(sW4 + d*64 + lane);
            unsigned long long w1 = *(const unsigned long long*)(sW4 + d*64 + lane + 32);
            #pragma unroll
            for (int e = 0; e < 8; e++) {
                unsigned long long av = sEa2[d*ET + eb + e];
                fma2(a0[e], av, w0);
                fma2(a1[e], av, w1);
            }
        }
        #pragma unroll 1
        for (int e = 0; e < 8; e++) {
            int eg = e0 + eb + e;
            int s = sIdx[eb + e], t = sIdx[ET + eb + e];
            float2 f0 = unpack2(a0[e]), f1 = unpack2(a1[e]);
            float2 xa0 = *(const float2*)(g_XA + s*C + 2*lane);
            float2 xa1 = *(const float2*)(g_XA + s*C + 2*lane + 64);
            float2 xb0 = *(const float2*)(g_XB + t*C + 2*lane);
            float2 xb1 = *(const float2*)(g_XB + t*C + 2*lane + 64);
            f0.x += xa0.x + xb0.x;  f0.y += xa0.y + xb0.y;
            f1.x += xa1.x + xb1.x;  f1.y += xa1.y + xb1.y;
            f0.x = f0.x > 0.0f ? f0.x : __expf(f0.x) - 1.0f;
            f0.y = f0.y > 0.0f ? f0.y : __expf(f0.y) - 1.0f;
            f1.x = f1.x > 0.0f ? f1.x : __expf(f1.x) - 1.0f;
            f1.y = f1.y > 0.0f ? f1.y : __expf(f1.y) - 1.0f;
            float mval = __uint_as_float((unsigned int)(sEa2[eb + e] & 0xffffffffull));
            float msk  = (mval < 8.0f) ? 1.0f : 0.0f;
            f0.x *= msk; f0.y *= msk; f1.x *= msk; f1.y *= msk;
            float2 xm0 = *(const float2*)(g_Xm + s*C + 2*lane);
            float2 xm1 = *(const float2*)(g_Xm + s*C + 2*lane + 64);
            float p = f0.x*xm0.x + f0.y*xm0.y + f1.x*xm1.x + f1.y*xm1.y;
            #pragma unroll
            for (int off = 16; off; off >>= 1) p += __shfl_xor_sync(0xffffffffu, p, off);
            *(float2*)(g_f + (size_t)eg*C + 2*lane)      = f0;
            *(float2*)(g_f + (size_t)eg*C + 2*lane + 64) = f1;
            if (lane == 0) {
                float av = tanhf(p);
                g_a[eg] = av;
                atomicAdd(&g_asum[s], av);
            }
        }
    }
}

// ---------------- K3: edge pass 2 — z = exp(a - asum[src]) * f, scatter ------
__global__ __launch_bounds__(256) void edge2_kernel(const int* __restrict__ ei) {
    int idx = blockIdx.x * 256 + threadIdx.x;    // E*32 threads, 1 float4 each
    int e = idx >> 5;
    if (e >= E) return;
    int q = idx & 31;
    int s = ei[e];
    float sc = __expf(g_a[e] - g_asum[s]);
    float4 f4 = *(const float4*)(g_f + (size_t)e*C + q*4);
    float zx = sc*f4.x, zy = sc*f4.y, zz = sc*f4.z, zw = sc*f4.w;
    asm volatile("red.global.add.v4.f32 [%0], {%1, %2, %3, %4};"
                 :: "l"(g_aggr + s*C + q*4), "f"(zx), "f"(zy), "f"(zz), "f"(zw)
                 : "memory");
}

// ---------------- K4: out = (x + aggr) @ Wu + bu -----------------------------
__global__ __launch_bounds__(128) void node_out_kernel(const float* __restrict__ x,
                                                       const float* __restrict__ Wu,
                                                       const float* __restrict__ bu,
                                                       float* __restrict__ out) {
    extern __shared__ unsigned char smem[];
    float2* sW2 = (float2*)smem;                                     // [128][64]
    unsigned long long* sX2 = (unsigned long long*)(smem + 65536);   // [128][33]
    int tid = threadIdx.x, lane = tid & 31, w = tid >> 5;
    const float2* W2 = (const float2*)Wu;
    for (int i = tid; i < C*64; i += 128) sW2[i] = W2[i];
    unsigned long long bi0 = pack2(bu[2*lane],      bu[2*lane + 1]);
    unsigned long long bi1 = pack2(bu[2*lane + 64], bu[2*lane + 65]);
    const int ntiles = (NN + 31) / 32;
    for (int tile = blockIdx.x; tile < ntiles; tile += gridDim.x) {
        int n0 = tile * 32;
        __syncthreads();
        for (int i = tid; i < C*32; i += 128) {
            int d = i & 127, n = i >> 7, ng = n0 + n;
            float v = (ng < NN) ? (x[ng*C + d] + g_aggr[ng*C + d]) : 0.0f;
            sX2[d*33 + n] = dup2(v);
        }
        __syncthreads();
        int nb = w * 8;
        unsigned long long a0[8], a1[8];
        #pragma unroll
        for (int e = 0; e < 8; e++) { a0[e] = bi0; a1[e] = bi1; }
        #pragma unroll 4
        for (int d = 0; d < C; d++) {
            unsigned long long w0 = *(const unsigned long long*)(sW2 + d*64 + lane);
            unsigned long long w1 = *(const unsigned long long*)(sW2 + d*64 + lane + 32);
            #pragma unroll
            for (int e = 0; e < 8; e++) {
                unsigned long long xv = sX2[d*33 + nb + e];
                fma2(a0[e], xv, w0);
                fma2(a1[e], xv, w1);
            }
        }
        #pragma unroll 1
        for (int e = 0; e < 8; e++) {
            int n = n0 + nb + e;
            if (n < NN) {
                *(float2*)(out + n*C + 2*lane)      = unpack2(a0[e]);
                *(float2*)(out + n*C + 2*lane + 64) = unpack2(a1[e]);
            }
        }
    }
}

// ---------------- host launcher ----------------------------------------------
extern "C" void kernel_launch(void* const* d_in, const int* in_sizes, int n_in,
                              void* d_out, int out_size) {
    const float* x   = (const float*)d_in[0];
    const int*   ei  = (const int*  )d_in[1];
    const float* ea  = (const float*)d_in[2];
    const float* Wf  = (const float*)d_in[3];
    const float* bf  = (const float*)d_in[4];
    const float* Wq  = (const float*)d_in[5];
    const float* Wk  = (const float*)d_in[6];
    const float* Wa  = (const float*)d_in[7];
    const float* Wu  = (const float*)d_in[8];
    const float* bu  = (const float*)d_in[9];
    float* out = (float*)d_out;

    (void)in_sizes; (void)n_in; (void)out_size;

    const int smem_node  = 65536 + 128*33*8;   // 99328
    const int smem_edge1 = 50688;
    cudaFuncSetAttribute(node_pre_kernel, cudaFuncAttributeMaxDynamicSharedMemorySize, smem_node);
    cudaFuncSetAttribute(node_out_kernel, cudaFuncAttributeMaxDynamicSharedMemorySize, smem_node);
    cudaFuncSetAttribute(edge1_kernel,    cudaFuncAttributeMaxDynamicSharedMemorySize, smem_edge1);

    prep_kernel<<<C, C>>>(Wf, Wq, Wk, Wa);
    zero_kernel<<<(NN*C + 255) / 256, 256>>>();
    node_pre_kernel<<<296, 128, smem_node>>>(x);
    edge1_kernel<<<592, 128, smem_edge1>>>(ea, ei, Wf, bf);
    edge2_kernel<<<(E*32) / 256, 256>>>(ei);
    node_out_kernel<<<296, 128, smem_node>>>(x, Wu, bu, out);
}

// round 2
// speedup vs baseline: 1.1506x; 1.1506x over previous
#include <cuda_runtime.h>

#define NN   50000
#define C    128
#define E    800000
#define EF   65
#define EAC  70
#define ET   32

typedef unsigned long long ull;

// ---------------- scratch (device globals; no allocation allowed) ------------
__device__ float g_A [C*C];           // Wf1 + Wf3
__device__ float g_B [C*C];           // Wf2 - Wf3
__device__ float g_M [C*C];           // scale * Wq diag(Wa) Wk^T
__device__ float g_XA[NN*C];          // x @ A
__device__ float g_XB[NN*C];          // x @ B
__device__ float g_Xm[NN*C];          // x @ M
__device__ float g_f [(size_t)E*C];   // per-edge f rows (409.6 MB)
__device__ float g_a [E];             // per-edge attention scalar
__device__ float g_asum[NN];          // segment sum of a over src
__device__ float g_aggr[NN*C];        // segment sum of z over src

// ---------------- packed fp32x2 helpers (Blackwell FFMA2) --------------------
__device__ __forceinline__ void fma2(ull &acc, ull a, ull b) {
    asm("fma.rn.f32x2 %0, %1, %2, %0;" : "+l"(acc) : "l"(a), "l"(b));
}
__device__ __forceinline__ ull dup2(float v) {
    unsigned int u = __float_as_uint(v);
    return ((ull)u << 32) | (ull)u;
}
__device__ __forceinline__ ull pack2(float x, float y) {
    return ((ull)__float_as_uint(y) << 32) | (ull)__float_as_uint(x);
}
__device__ __forceinline__ float2 unpack2(ull p) {
    float2 r;
    r.x = __uint_as_float((unsigned int)(p & 0xffffffffull));
    r.y = __uint_as_float((unsigned int)(p >> 32));
    return r;
}

// ---------------- K0: fold weights ------------------------------------------
__global__ void prep_kernel(const float* __restrict__ Wf, const float* __restrict__ Wq,
                            const float* __restrict__ Wk, const float* __restrict__ Wa) {
    int d = blockIdx.x;      // 0..127
    int c = threadIdx.x;     // 0..127
    g_A[d*C + c] = Wf[d*C + c]        + Wf[(256+d)*C + c];
    g_B[d*C + c] = Wf[(128+d)*C + c]  - Wf[(256+d)*C + c];
    __shared__ float sWa[C], sWq[C];
    sWa[c] = Wa[c];
    sWq[c] = Wq[d*C + c];
    __syncthreads();
    float acc = 0.0f;
    #pragma unroll 4
    for (int k = 0; k < C; k++) acc += sWq[k] * sWa[k] * Wk[c*C + k];
    g_M[d*C + c] = acc * 0.08838834764831845f;   // 128^-0.5
}

// ---------------- zero accumulators ------------------------------------------
__global__ void zero_kernel() {
    int i = blockIdx.x * blockDim.x + threadIdx.x;
    if (i < NN*C) g_aggr[i] = 0.0f;
    if (i < NN)   g_asum[i] = 0.0f;
}

// ============ shared node-GEMM microkernel scheme =============================
// 256 thr (8 warps), 32-node tile, warp = 4 nodes x 128 ch.
// lane owns channels [4*lane, 4*lane+3]. Weights as float4 rows in smem.
// smem: sW [128][32] float4 = 65536 B ; sX2 dup'd u64 [128][33] = 33792 B.
#define NODE_SMEM (65536 + 128*33*8)

__device__ __forceinline__ void node_gemm_tile(const ull* sX2, const ulonglong2* sWu2,
                                               int lane, int nb, ull bi0, ull bi1,
                                               ull a0[4], ull a1[4]) {
    #pragma unroll
    for (int e = 0; e < 4; e++) { a0[e] = bi0; a1[e] = bi1; }
    #pragma unroll 8
    for (int d = 0; d < C; d++) {
        ulonglong2 wv = sWu2[d*32 + lane];
        #pragma unroll
        for (int e = 0; e < 4; e++) {
            ull xv = sX2[d*33 + nb + e];
            fma2(a0[e], xv, wv.x);
            fma2(a1[e], xv, wv.y);
        }
    }
}

// ---------------- K1: node precompute XA, XB, Xm -----------------------------
__global__ __launch_bounds__(256, 2) void node_pre_kernel(const float* __restrict__ x) {
    extern __shared__ unsigned char smem[];
    float4*    sW4  = (float4*)smem;
    ulonglong2* sWu2 = (ulonglong2*)smem;
    ull*       sX2  = (ull*)(smem + 65536);
    int tid = threadIdx.x, lane = tid & 31, w = tid >> 5;
    const float* Ws[3] = {g_A, g_B, g_M};
    float*       Ys[3] = {g_XA, g_XB, g_Xm};
    const int ntiles = (NN + 31) / 32;
    for (int m = 0; m < 3; m++) {
        __syncthreads();
        const float4* W4 = (const float4*)Ws[m];
        for (int i = tid; i < C*32; i += 256) sW4[i] = W4[i];
        float* Y = Ys[m];
        for (int tile = blockIdx.x; tile < ntiles; tile += gridDim.x) {
            int n0 = tile * 32;
            __syncthreads();
            for (int i = tid; i < C*32; i += 256) {
                int d = i & 127, n = i >> 7, ng = n0 + n;
                float v = (ng < NN) ? x[(size_t)ng*C + d] : 0.0f;
                sX2[d*33 + n] = dup2(v);
            }
            __syncthreads();
            int nb = w * 4;
            ull a0[4], a1[4];
            node_gemm_tile(sX2, sWu2, lane, nb, 0ull, 0ull, a0, a1);
            #pragma unroll 1
            for (int e = 0; e < 4; e++) {
                int n = n0 + nb + e;
                if (n < NN) {
                    float2 f0 = unpack2(a0[e]), f1 = unpack2(a1[e]);
                    float4 o; o.x = f0.x; o.y = f0.y; o.z = f1.x; o.w = f1.y;
                    *(float4*)(Y + (size_t)n*C + 4*lane) = o;
                }
            }
        }
    }
}

// ---------------- K2: edge pass 1 — f, a, a_sum ------------------------------
// 256 thr (8 warps), 32 edges/tile, warp = 4 edges x 128 ch (lane: 4 contig ch)
__global__ __launch_bounds__(256, 4) void edge1_kernel(const float* __restrict__ ea,
                                                       const int*   __restrict__ ei,
                                                       const float* __restrict__ Wf,
                                                       const float* __restrict__ bf) {
    extern __shared__ unsigned char smem[];
    float4*     sW4  = (float4*)smem;                       // [65][32] f4 = 33280 B
    ulonglong2* sWu2 = (ulonglong2*)smem;
    ull*        sEa2 = (ull*)(smem + 33280);                // [65][32]   = 16640 B
    float4*     sBf4 = (float4*)(smem + 49920);             // [32]       = 512 B
    int*        sIdx = (int*)(smem + 50432);                // [64]       = 256 B
    int tid = threadIdx.x, lane = tid & 31, w = tid >> 5;

    for (int i = tid; i < EF*32; i += 256) {
        int d = i >> 5, l = i & 31;
        sW4[i] = *(const float4*)(Wf + (size_t)(3*C + d)*C + 4*l);
    }
    if (tid < 32) sBf4[tid] = *(const float4*)(bf + 4*tid);
    __syncthreads();
    float4 b4 = sBf4[lane];
    ull bi0 = pack2(b4.x, b4.y), bi1 = pack2(b4.z, b4.w);

    const int ntiles = E / ET;   // 25000
    for (int tile = blockIdx.x; tile < ntiles; tile += gridDim.x) {
        int e0 = tile * ET;
        __syncthreads();
        if (tid < ET)           sIdx[tid] = ei[e0 + tid];
        else if (tid < 2*ET)    sIdx[tid] = ei[E + e0 + tid - ET];
        for (int i = tid; i < EF*ET; i += 256) {
            int e = i & 31, d = i >> 5;
            sEa2[d*ET + e] = dup2(ea[(size_t)(e0 + e)*EAC + d]);
        }
        __syncthreads();

        int eb = w * 4;
        ull a0[4], a1[4];
        #pragma unroll
        for (int e = 0; e < 4; e++) { a0[e] = bi0; a1[e] = bi1; }
        #pragma unroll 5
        for (int d = 0; d < EF; d++) {
            ulonglong2 wv = sWu2[d*32 + lane];
            #pragma unroll
            for (int e = 0; e < 4; e++) {
                ull av = sEa2[d*ET + eb + e];
                fma2(a0[e], av, wv.x);
                fma2(a1[e], av, wv.y);
            }
        }
        #pragma unroll 1
        for (int e = 0; e < 4; e++) {
            int eg = e0 + eb + e;
            int s = sIdx[eb + e], t = sIdx[ET + eb + e];
            float2 f0 = unpack2(a0[e]), f1 = unpack2(a1[e]);
            float4 xa = __ldg((const float4*)(g_XA + (size_t)s*C + 4*lane));
            float4 xb = __ldg((const float4*)(g_XB + (size_t)t*C + 4*lane));
            float4 xm = __ldg((const float4*)(g_Xm + (size_t)s*C + 4*lane));
            float v0 = f0.x + xa.x + xb.x;
            float v1 = f0.y + xa.y + xb.y;
            float v2 = f1.x + xa.z + xb.z;
            float v3 = f1.y + xa.w + xb.w;
            v0 = v0 > 0.0f ? v0 : __expf(v0) - 1.0f;
            v1 = v1 > 0.0f ? v1 : __expf(v1) - 1.0f;
            v2 = v2 > 0.0f ? v2 : __expf(v2) - 1.0f;
            v3 = v3 > 0.0f ? v3 : __expf(v3) - 1.0f;
            float mval = __uint_as_float((unsigned int)(sEa2[eb + e] & 0xffffffffull));
            float msk  = (mval < 8.0f) ? 1.0f : 0.0f;
            v0 *= msk; v1 *= msk; v2 *= msk; v3 *= msk;
            float p = v0*xm.x + v1*xm.y + v2*xm.z + v3*xm.w;
            #pragma unroll
            for (int off = 16; off; off >>= 1) p += __shfl_xor_sync(0xffffffffu, p, off);
            float4 o; o.x = v0; o.y = v1; o.z = v2; o.w = v3;
            *(float4*)(g_f + (size_t)eg*C + 4*lane) = o;
            if (lane == 0) {
                float av = tanhf(p);
                g_a[eg] = av;
                atomicAdd(&g_asum[s], av);
            }
        }
    }
}

// ---------------- K3: edge pass 2 — z = exp(a - asum[src]) * f, scatter ------
__global__ __launch_bounds__(256) void edge2_kernel(const int* __restrict__ ei) {
    int idx = blockIdx.x * 256 + threadIdx.x;    // E*32 threads, 1 float4 each
    int e = idx >> 5;
    if (e >= E) return;
    int q = idx & 31;
    int s = ei[e];
    float sc = __expf(g_a[e] - g_asum[s]);
    float4 f4 = *(const float4*)(g_f + (size_t)e*C + q*4);
    float zx = sc*f4.x, zy = sc*f4.y, zz = sc*f4.z, zw = sc*f4.w;
    asm volatile("red.global.add.v4.f32 [%0], {%1, %2, %3, %4};"
                 :: "l"(g_aggr + (size_t)s*C + q*4), "f"(zx), "f"(zy), "f"(zz), "f"(zw)
                 : "memory");
}

// ---------------- K4: out = (x + aggr) @ Wu + bu -----------------------------
__global__ __launch_bounds__(256, 2) void node_out_kernel(const float* __restrict__ x,
                                                          const float* __restrict__ Wu,
                                                          const float* __restrict__ bu,
                                                          float* __restrict__ out) {
    extern __shared__ unsigned char smem[];
    float4*     sW4  = (float4*)smem;
    ulonglong2* sWu2 = (ulonglong2*)smem;
    ull*        sX2  = (ull*)(smem + 65536);
    int tid = threadIdx.x, lane = tid & 31, w = tid >> 5;
    const float4* W4 = (const float4*)Wu;
    for (int i = tid; i < C*32; i += 256) sW4[i] = W4[i];
    float4 b4 = *(const float4*)(bu + 4*lane);
    ull bi0 = pack2(b4.x, b4.y), bi1 = pack2(b4.z, b4.w);
    const int ntiles = (NN + 31) / 32;
    for (int tile = blockIdx.x; tile < ntiles; tile += gridDim.x) {
        int n0 = tile * 32;
        __syncthreads();
        for (int i = tid; i < C*32; i += 256) {
            int d = i & 127, n = i >> 7, ng = n0 + n;
            float v = (ng < NN) ? (x[(size_t)ng*C + d] + g_aggr[(size_t)ng*C + d]) : 0.0f;
            sX2[d*33 + n] = dup2(v);
        }
        __syncthreads();
        int nb = w * 4;
        ull a0[4], a1[4];
        node_gemm_tile(sX2, sWu2, lane, nb, bi0, bi1, a0, a1);
        #pragma unroll 1
        for (int e = 0; e < 4; e++) {
            int n = n0 + nb + e;
            if (n < NN) {
                float2 f0 = unpack2(a0[e]), f1 = unpack2(a1[e]);
                float4 o; o.x = f0.x; o.y = f0.y; o.z = f1.x; o.w = f1.y;
                *(float4*)(out + (size_t)n*C + 4*lane) = o;
            }
        }
    }
}

// ---------------- host launcher ----------------------------------------------
extern "C" void kernel_launch(void* const* d_in, const int* in_sizes, int n_in,
                              void* d_out, int out_size) {
    const float* x   = (const float*)d_in[0];
    const int*   ei  = (const int*  )d_in[1];
    const float* ea  = (const float*)d_in[2];
    const float* Wf  = (const float*)d_in[3];
    const float* bf  = (const float*)d_in[4];
    const float* Wq  = (const float*)d_in[5];
    const float* Wk  = (const float*)d_in[6];
    const float* Wa  = (const float*)d_in[7];
    const float* Wu  = (const float*)d_in[8];
    const float* bu  = (const float*)d_in[9];
    float* out = (float*)d_out;

    (void)in_sizes; (void)n_in; (void)out_size;

    const int smem_node  = NODE_SMEM;     // 99328
    const int smem_edge1 = 50688;
    cudaFuncSetAttribute(node_pre_kernel, cudaFuncAttributeMaxDynamicSharedMemorySize, smem_node);
    cudaFuncSetAttribute(node_out_kernel, cudaFuncAttributeMaxDynamicSharedMemorySize, smem_node);
    cudaFuncSetAttribute(edge1_kernel,    cudaFuncAttributeMaxDynamicSharedMemorySize, smem_edge1);

    prep_kernel<<<C, C>>>(Wf, Wq, Wk, Wa);
    zero_kernel<<<(NN*C + 255) / 256, 256>>>();
    node_pre_kernel<<<304, 256, smem_node>>>(x);
    edge1_kernel<<<608, 256, smem_edge1>>>(ea, ei, Wf, bf);
    edge2_kernel<<<(E*32) / 256, 256>>>(ei);
    node_out_kernel<<<304, 256, smem_node>>>(x, Wu, bu, out);
}

// round 3
// speedup vs baseline: 1.2229x; 1.0629x over previous
#include <cuda_runtime.h>

#define NN   50000
#define C    128
#define E    800000
#define EF   65
#define EAC  70
#define ET   64

typedef unsigned long long ull;

// ---------------- scratch (device globals; no allocation allowed) ------------
__device__ float g_A [C*C];           // Wf1 + Wf3
__device__ float g_B [C*C];           // Wf2 - Wf3
__device__ float g_M [C*C];           // scale * Wq diag(Wa) Wk^T
__device__ float g_XA[NN*C];          // x @ A
__device__ float g_XB[NN*C];          // x @ B
__device__ float g_Xm[NN*C];          // x @ M
__device__ float g_f [(size_t)E*C];   // per-edge f rows (409.6 MB)
__device__ float g_a [E];             // per-edge attention scalar
__device__ float g_asum[NN];          // segment sum of a over src
__device__ float g_aggr[NN*C];        // segment sum of z over src

// ---------------- packed fp32x2 helpers (Blackwell FFMA2) --------------------
__device__ __forceinline__ void fma2(ull &acc, ull a, ull b) {
    asm("fma.rn.f32x2 %0, %1, %2, %0;" : "+l"(acc) : "l"(a), "l"(b));
}
__device__ __forceinline__ ull dup2(float v) {
    unsigned int u = __float_as_uint(v);
    return ((ull)u << 32) | (ull)u;
}
__device__ __forceinline__ ull pack2(float x, float y) {
    return ((ull)__float_as_uint(y) << 32) | (ull)__float_as_uint(x);
}
__device__ __forceinline__ float2 unpack2(ull p) {
    float2 r;
    r.x = __uint_as_float((unsigned int)(p & 0xffffffffull));
    r.y = __uint_as_float((unsigned int)(p >> 32));
    return r;
}

// ---------------- K0: fold weights ------------------------------------------
__global__ void prep_kernel(const float* __restrict__ Wf, const float* __restrict__ Wq,
                            const float* __restrict__ Wk, const float* __restrict__ Wa) {
    int d = blockIdx.x;      // 0..127
    int c = threadIdx.x;     // 0..127
    g_A[d*C + c] = Wf[d*C + c]        + Wf[(256+d)*C + c];
    g_B[d*C + c] = Wf[(128+d)*C + c]  - Wf[(256+d)*C + c];
    __shared__ float sWa[C], sWq[C];
    sWa[c] = Wa[c];
    sWq[c] = Wq[d*C + c];
    __syncthreads();
    float acc = 0.0f;
    #pragma unroll 4
    for (int k = 0; k < C; k++) acc += sWq[k] * sWa[k] * Wk[c*C + k];
    g_M[d*C + c] = acc * 0.08838834764831845f;   // 128^-0.5
}

// ---------------- zero accumulators ------------------------------------------
__global__ void zero_kernel() {
    int i = blockIdx.x * blockDim.x + threadIdx.x;
    if (i < NN*C) g_aggr[i] = 0.0f;
    if (i < NN)   g_asum[i] = 0.0f;
}

// ============ shared node-GEMM microkernel scheme =============================
// 256 thr (8 warps), 32-node tile, warp = 4 nodes x 128 ch.
// lane owns channels [4*lane, 4*lane+3]. Weights as float4 rows in smem.
#define NODE_SMEM (65536 + 128*33*8)

__device__ __forceinline__ void node_gemm_tile(const ull* sX2, const ulonglong2* sWu2,
                                               int lane, int nb, ull bi0, ull bi1,
                                               ull a0[4], ull a1[4]) {
    #pragma unroll
    for (int e = 0; e < 4; e++) { a0[e] = bi0; a1[e] = bi1; }
    #pragma unroll 8
    for (int d = 0; d < C; d++) {
        ulonglong2 wv = sWu2[d*32 + lane];
        #pragma unroll
        for (int e = 0; e < 4; e++) {
            ull xv = sX2[d*33 + nb + e];
            fma2(a0[e], xv, wv.x);
            fma2(a1[e], xv, wv.y);
        }
    }
}

// ---------------- K1: node precompute XA, XB, Xm -----------------------------
__global__ __launch_bounds__(256, 2) void node_pre_kernel(const float* __restrict__ x) {
    extern __shared__ unsigned char smem[];
    float4*     sW4  = (float4*)smem;
    ulonglong2* sWu2 = (ulonglong2*)smem;
    ull*        sX2  = (ull*)(smem + 65536);
    int tid = threadIdx.x, lane = tid & 31, w = tid >> 5;
    const float* Ws[3] = {g_A, g_B, g_M};
    float*       Ys[3] = {g_XA, g_XB, g_Xm};
    const int ntiles = (NN + 31) / 32;
    for (int m = 0; m < 3; m++) {
        __syncthreads();
        const float4* W4 = (const float4*)Ws[m];
        for (int i = tid; i < C*32; i += 256) sW4[i] = W4[i];
        float* Y = Ys[m];
        for (int tile = blockIdx.x; tile < ntiles; tile += gridDim.x) {
            int n0 = tile * 32;
            __syncthreads();
            for (int i = tid; i < C*32; i += 256) {
                int d = i & 127, n = i >> 7, ng = n0 + n;
                float v = (ng < NN) ? x[(size_t)ng*C + d] : 0.0f;
                sX2[d*33 + n] = dup2(v);
            }
            __syncthreads();
            int nb = w * 4;
            ull a0[4], a1[4];
            node_gemm_tile(sX2, sWu2, lane, nb, 0ull, 0ull, a0, a1);
            #pragma unroll 1
            for (int e = 0; e < 4; e++) {
                int n = n0 + nb + e;
                if (n < NN) {
                    float2 f0 = unpack2(a0[e]), f1 = unpack2(a1[e]);
                    float4 o; o.x = f0.x; o.y = f0.y; o.z = f1.x; o.w = f1.y;
                    *(float4*)(Y + (size_t)n*C + 4*lane) = o;
                }
            }
        }
    }
}

// ---------------- K2: edge pass 1 — f, a, a_sum ------------------------------
// 256 thr (8 warps), 64 edges/tile, warp = 8 edges x 128 ch (lane: 4 contig ch)
// smem layout:
//   sW4  [65][32] float4   @ 0        33280 B
//   sEa  [65][65] float    @ 33280    16900 B  (row stride 65 -> 2-way store conflict)
//   sBf4 [32]  float4      @ 50192      512 B
//   sIdx [128] int         @ 50704      512 B
#define E1_SW   0
#define E1_SEA  33280
#define E1_SBF  50192
#define E1_SIDX 50704
#define E1_SMEM 51216

__global__ __launch_bounds__(256, 4) void edge1_kernel(const float* __restrict__ ea,
                                                       const int*   __restrict__ ei,
                                                       const float* __restrict__ Wf,
                                                       const float* __restrict__ bf) {
    extern __shared__ unsigned char smem[];
    float4*     sW4  = (float4*)(smem + E1_SW);
    ulonglong2* sWu2 = (ulonglong2*)(smem + E1_SW);
    float*      sEa  = (float*)(smem + E1_SEA);
    float4*     sBf4 = (float4*)(smem + E1_SBF);
    int*        sIdx = (int*)(smem + E1_SIDX);
    int tid = threadIdx.x, lane = tid & 31, w = tid >> 5;

    for (int i = tid; i < EF*32; i += 256) {
        int d = i >> 5, l = i & 31;
        sW4[i] = *(const float4*)(Wf + (size_t)(3*C + d)*C + 4*l);
    }
    if (tid < 32) sBf4[tid] = *(const float4*)(bf + 4*tid);
    __syncthreads();
    float4 b4 = sBf4[lane];
    ull bi0 = pack2(b4.x, b4.y), bi1 = pack2(b4.z, b4.w);

    const int eb = w * 8;                 // this warp's 8 edges within the tile
    const int ntiles = E / ET;            // 12500
    for (int tile = blockIdx.x; tile < ntiles; tile += gridDim.x) {
        int e0 = tile * ET;
        __syncthreads();
        if (tid < ET)           sIdx[tid] = ei[e0 + tid];
        else if (tid < 2*ET)    sIdx[tid] = ei[E + e0 + tid - ET];
        // coalesced ea staging: this warp loads its own 8 edges' rows
        #pragma unroll 1
        for (int i = 0; i < 8; i++) {
            const float* row = ea + (size_t)(e0 + eb + i)*EAC;
            float2 v = *(const float2*)(row + 2*lane);          // 64 floats
            sEa[(2*lane)*65   + eb + i] = v.x;
            sEa[(2*lane+1)*65 + eb + i] = v.y;
            if (lane == 0) sEa[64*65 + eb + i] = row[64];       // d = 64
        }
        __syncthreads();

        ull a0[8], a1[8];
        #pragma unroll
        for (int e = 0; e < 8; e++) { a0[e] = bi0; a1[e] = bi1; }
        #pragma unroll 5
        for (int d = 0; d < EF; d++) {
            ulonglong2 wv = sWu2[d*32 + lane];
            const float* er = sEa + d*65 + eb;
            #pragma unroll
            for (int e = 0; e < 8; e++) {
                ull av = dup2(er[e]);          // LDS.32 broadcast + reg dup
                fma2(a0[e], av, wv.x);
                fma2(a1[e], av, wv.y);
            }
        }
        #pragma unroll 1
        for (int e = 0; e < 8; e++) {
            int eg = e0 + eb + e;
            int s = sIdx[eb + e], t = sIdx[ET + eb + e];
            float2 f0 = unpack2(a0[e]), f1 = unpack2(a1[e]);
            float4 xa = __ldg((const float4*)(g_XA + (size_t)s*C + 4*lane));
            float4 xb = __ldg((const float4*)(g_XB + (size_t)t*C + 4*lane));
            float4 xm = __ldg((const float4*)(g_Xm + (size_t)s*C + 4*lane));
            float v0 = f0.x + xa.x + xb.x;
            float v1 = f0.y + xa.y + xb.y;
            float v2 = f1.x + xa.z + xb.z;
            float v3 = f1.y + xa.w + xb.w;
            v0 = v0 > 0.0f ? v0 : __expf(v0) - 1.0f;
            v1 = v1 > 0.0f ? v1 : __expf(v1) - 1.0f;
            v2 = v2 > 0.0f ? v2 : __expf(v2) - 1.0f;
            v3 = v3 > 0.0f ? v3 : __expf(v3) - 1.0f;
            float msk = (sEa[eb + e] < 8.0f) ? 1.0f : 0.0f;     // sEa[0][e]
            v0 *= msk; v1 *= msk; v2 *= msk; v3 *= msk;
            float p = v0*xm.x + v1*xm.y + v2*xm.z + v3*xm.w;
            #pragma unroll
            for (int off = 16; off; off >>= 1) p += __shfl_xor_sync(0xffffffffu, p, off);
            float4 o; o.x = v0; o.y = v1; o.z = v2; o.w = v3;
            *(float4*)(g_f + (size_t)eg*C + 4*lane) = o;
            if (lane == 0) {
                float av = tanhf(p);
                g_a[eg] = av;
                atomicAdd(&g_asum[s], av);
            }
        }
    }
}

// ---------------- K3: edge pass 2 — z = exp(a - asum[src]) * f, scatter ------
__global__ __launch_bounds__(256) void edge2_kernel(const int* __restrict__ ei) {
    int idx = blockIdx.x * 256 + threadIdx.x;    // E*32 threads, 1 float4 each
    int e = idx >> 5;
    if (e >= E) return;
    int q = idx & 31;
    int s = ei[e];
    float sc = __expf(g_a[e] - g_asum[s]);
    float4 f4 = *(const float4*)(g_f + (size_t)e*C + q*4);
    float zx = sc*f4.x, zy = sc*f4.y, zz = sc*f4.z, zw = sc*f4.w;
    asm volatile("red.global.add.v4.f32 [%0], {%1, %2, %3, %4};"
                 :: "l"(g_aggr + (size_t)s*C + q*4), "f"(zx), "f"(zy), "f"(zz), "f"(zw)
                 : "memory");
}

// ---------------- K4: out = (x + aggr) @ Wu + bu -----------------------------
__global__ __launch_bounds__(256, 2) void node_out_kernel(const float* __restrict__ x,
                                                          const float* __restrict__ Wu,
                                                          const float* __restrict__ bu,
                                                          float* __restrict__ out) {
    extern __shared__ unsigned char smem[];
    float4*     sW4  = (float4*)smem;
    ulonglong2* sWu2 = (ulonglong2*)smem;
    ull*        sX2  = (ull*)(smem + 65536);
    int tid = threadIdx.x, lane = tid & 31, w = tid >> 5;
    const float4* W4 = (const float4*)Wu;
    for (int i = tid; i < C*32; i += 256) sW4[i] = W4[i];
    float4 b4 = *(const float4*)(bu + 4*lane);
    ull bi0 = pack2(b4.x, b4.y), bi1 = pack2(b4.z, b4.w);
    const int ntiles = (NN + 31) / 32;
    for (int tile = blockIdx.x; tile < ntiles; tile += gridDim.x) {
        int n0 = tile * 32;
        __syncthreads();
        for (int i = tid; i < C*32; i += 256) {
            int d = i & 127, n = i >> 7, ng = n0 + n;
            float v = (ng < NN) ? (x[(size_t)ng*C + d] + g_aggr[(size_t)ng*C + d]) : 0.0f;
            sX2[d*33 + n] = dup2(v);
        }
        __syncthreads();
        int nb = w * 4;
        ull a0[4], a1[4];
        node_gemm_tile(sX2, sWu2, lane, nb, bi0, bi1, a0, a1);
        #pragma unroll 1
        for (int e = 0; e < 4; e++) {
            int n = n0 + nb + e;
            if (n < NN) {
                float2 f0 = unpack2(a0[e]), f1 = unpack2(a1[e]);
                float4 o; o.x = f0.x; o.y = f0.y; o.z = f1.x; o.w = f1.y;
                *(float4*)(out + (size_t)n*C + 4*lane) = o;
            }
        }
    }
}

// ---------------- host launcher ----------------------------------------------
extern "C" void kernel_launch(void* const* d_in, const int* in_sizes, int n_in,
                              void* d_out, int out_size) {
    const float* x   = (const float*)d_in[0];
    const int*   ei  = (const int*  )d_in[1];
    const float* ea  = (const float*)d_in[2];
    const float* Wf  = (const float*)d_in[3];
    const float* bf  = (const float*)d_in[4];
    const float* Wq  = (const float*)d_in[5];
    const float* Wk  = (const float*)d_in[6];
    const float* Wa  = (const float*)d_in[7];
    const float* Wu  = (const float*)d_in[8];
    const float* bu  = (const float*)d_in[9];
    float* out = (float*)d_out;

    (void)in_sizes; (void)n_in; (void)out_size;

    cudaFuncSetAttribute(node_pre_kernel, cudaFuncAttributeMaxDynamicSharedMemorySize, NODE_SMEM);
    cudaFuncSetAttribute(node_out_kernel, cudaFuncAttributeMaxDynamicSharedMemorySize, NODE_SMEM);
    cudaFuncSetAttribute(edge1_kernel,    cudaFuncAttributeMaxDynamicSharedMemorySize, E1_SMEM);

    prep_kernel<<<C, C>>>(Wf, Wq, Wk, Wa);
    zero_kernel<<<(NN*C + 255) / 256, 256>>>();
    node_pre_kernel<<<304, 256, NODE_SMEM>>>(x);
    edge1_kernel<<<608, 256, E1_SMEM>>>(ea, ei, Wf, bf);
    edge2_kernel<<<(E*32) / 256, 256>>>(ei);
    node_out_kernel<<<304, 256, NODE_SMEM>>>(x, Wu, bu, out);
}

// round 6
// speedup vs baseline: 1.4755x; 1.2065x over previous
#include <cuda_runtime.h>

#define NN   50000
#define C    128
#define E    800000
#define EF   65
#define EAC  70
#define ET   64

typedef unsigned long long ull;

// ---------------- scratch (device globals; no allocation allowed) ------------
__device__ float g_A [C*C];           // Wf1 + Wf3
__device__ float g_B [C*C];           // Wf2 - Wf3
__device__ float g_M [C*C];           // scale * Wq diag(Wa) Wk^T
__device__ float g_XA[NN*C];          // x @ A
__device__ float g_XB[NN*C];          // x @ B
__device__ float g_Xm[NN*C];          // x @ M
__device__ float g_asum[NN];          // segment sum of a over src
__device__ float g_aggr[NN*C];        // segment sum of exp(a)*f over src

// ---------------- packed fp32x2 helpers (Blackwell FFMA2) --------------------
__device__ __forceinline__ void fma2(ull &acc, ull a, ull b) {
    asm("fma.rn.f32x2 %0, %1, %2, %0;" : "+l"(acc) : "l"(a), "l"(b));
}
__device__ __forceinline__ ull dup2(float v) {
    unsigned int u = __float_as_uint(v);
    return ((ull)u << 32) | (ull)u;
}
__device__ __forceinline__ ull pack2(float x, float y) {
    return ((ull)__float_as_uint(y) << 32) | (ull)__float_as_uint(x);
}
__device__ __forceinline__ float2 unpack2(ull p) {
    float2 r;
    r.x = __uint_as_float((unsigned int)(p & 0xffffffffull));
    r.y = __uint_as_float((unsigned int)(p >> 32));
    return r;
}
// tanh via exp, saturates correctly at +-1 (exp->inf => 1-0; exp->0 => -1)
__device__ __forceinline__ float tanh_fast(float x) {
    float t = __expf(2.0f * x);
    return 1.0f - __fdividef(2.0f, t + 1.0f);
}

// ---------------- K0: fold weights ------------------------------------------
__global__ void prep_kernel(const float* __restrict__ Wf, const float* __restrict__ Wq,
                            const float* __restrict__ Wk, const float* __restrict__ Wa) {
    int d = blockIdx.x;      // 0..127
    int c = threadIdx.x;     // 0..127
    g_A[d*C + c] = Wf[d*C + c]        + Wf[(256+d)*C + c];
    g_B[d*C + c] = Wf[(128+d)*C + c]  - Wf[(256+d)*C + c];
    __shared__ float sWa[C], sWq[C];
    sWa[c] = Wa[c];
    sWq[c] = Wq[d*C + c];
    __syncthreads();
    float acc = 0.0f;
    #pragma unroll 4
    for (int k = 0; k < C; k++) acc += sWq[k] * sWa[k] * Wk[c*C + k];
    g_M[d*C + c] = acc * 0.08838834764831845f;   // 128^-0.5
}

// ---------------- zero accumulators ------------------------------------------
__global__ void zero_kernel() {
    int i = blockIdx.x * blockDim.x + threadIdx.x;
    if (i < NN*C) g_aggr[i] = 0.0f;
    if (i < NN)   g_asum[i] = 0.0f;
}

// ============ shared node-GEMM microkernel scheme =============================
#define NODE_SMEM (65536 + 128*33*8)

__device__ __forceinline__ void node_gemm_tile(const ull* sX2, const ulonglong2* sWu2,
                                               int lane, int nb, ull bi0, ull bi1,
                                               ull a0[4], ull a1[4]) {
    #pragma unroll
    for (int e = 0; e < 4; e++) { a0[e] = bi0; a1[e] = bi1; }
    #pragma unroll 8
    for (int d = 0; d < C; d++) {
        ulonglong2 wv = sWu2[d*32 + lane];
        #pragma unroll
        for (int e = 0; e < 4; e++) {
            ull xv = sX2[d*33 + nb + e];
            fma2(a0[e], xv, wv.x);
            fma2(a1[e], xv, wv.y);
        }
    }
}

// ---------------- K1: node precompute XA, XB, Xm -----------------------------
__global__ __launch_bounds__(256, 2) void node_pre_kernel(const float* __restrict__ x) {
    extern __shared__ unsigned char smem[];
    float4*     sW4  = (float4*)smem;
    ulonglong2* sWu2 = (ulonglong2*)smem;
    ull*        sX2  = (ull*)(smem + 65536);
    int tid = threadIdx.x, lane = tid & 31, w = tid >> 5;
    const float* Ws[3] = {g_A, g_B, g_M};
    float*       Ys[3] = {g_XA, g_XB, g_Xm};
    const int ntiles = (NN + 31) / 32;
    for (int m = 0; m < 3; m++) {
        __syncthreads();
        const float4* W4 = (const float4*)Ws[m];
        for (int i = tid; i < C*32; i += 256) sW4[i] = W4[i];
        float* Y = Ys[m];
        for (int tile = blockIdx.x; tile < ntiles; tile += gridDim.x) {
            int n0 = tile * 32;
            __syncthreads();
            for (int i = tid; i < C*32; i += 256) {
                int d = i & 127, n = i >> 7, ng = n0 + n;
                float v = (ng < NN) ? x[(size_t)ng*C + d] : 0.0f;
                sX2[d*33 + n] = dup2(v);
            }
            __syncthreads();
            int nb = w * 4;
            ull a0[4], a1[4];
            node_gemm_tile(sX2, sWu2, lane, nb, 0ull, 0ull, a0, a1);
            #pragma unroll 1
            for (int e = 0; e < 4; e++) {
                int n = n0 + nb + e;
                if (n < NN) {
                    float2 f0 = unpack2(a0[e]), f1 = unpack2(a1[e]);
                    float4 o; o.x = f0.x; o.y = f0.y; o.z = f1.x; o.w = f1.y;
                    *(float4*)(Y + (size_t)n*C + 4*lane) = o;
                }
            }
        }
    }
}

// ---------------- K2: edge pass — f, a, scatter exp(a)*f and a ----------------
// 256 thr (8 warps), 64 edges/tile, warp = 8 edges (4 edge-pairs) x 128 ch.
// smem layout (all wide regions 16B-aligned):
//   sW4  [65][32] float4  @ 0      33280 B
//   sEa2 [65][33] u64     @ 33280  17160 B  (u64 = edge-pair {2p, 2p+1})
//   sBf4 [32]  float4     @ 50448    512 B  (padded: 50440 -> 50448 for 16B align)
//   sIdx [128] int        @ 50960    512 B
#define E1_SW   0
#define E1_SEA  33280
#define E1_SBF  50448
#define E1_SIDX 50960
#define E1_SMEM 51472

__global__ __launch_bounds__(256, 4) void edge1_kernel(const float* __restrict__ ea,
                                                       const int*   __restrict__ ei,
                                                       const float* __restrict__ Wf,
                                                       const float* __restrict__ bf) {
    extern __shared__ unsigned char smem[];
    float4*     sW4  = (float4*)(smem + E1_SW);
    ull*        sEa2 = (ull*)(smem + E1_SEA);
    float*      sEaF = (float*)(smem + E1_SEA);
    float4*     sBf4 = (float4*)(smem + E1_SBF);
    int*        sIdx = (int*)(smem + E1_SIDX);
    int tid = threadIdx.x, lane = tid & 31, w = tid >> 5;

    for (int i = tid; i < EF*32; i += 256) {
        int d = i >> 5, l = i & 31;
        sW4[i] = *(const float4*)(Wf + (size_t)(3*C + d)*C + 4*l);
    }
    if (tid < 32) sBf4[tid] = *(const float4*)(bf + 4*tid);
    __syncthreads();
    float4 b4 = sBf4[lane];
    ull bi0 = dup2(b4.x), bi1 = dup2(b4.y), bi2 = dup2(b4.z), bi3 = dup2(b4.w);

    const int eb = w * 8;                 // this warp's 8 edges within the tile
    const int pb = w * 4;                 // this warp's 4 edge-pairs
    const int ntiles = E / ET;            // 12500
    for (int tile = blockIdx.x; tile < ntiles; tile += gridDim.x) {
        int e0 = tile * ET;
        __syncthreads();
        if (tid < ET)           sIdx[tid] = ei[e0 + tid];
        else if (tid < 2*ET)    sIdx[tid] = ei[E + e0 + tid - ET];
        // coalesced ea staging: pair-interleaved [d][pair]{lo,hi}
        #pragma unroll 1
        for (int i = 0; i < 8; i++) {
            int e = eb + i, pr = e >> 1, par = e & 1;
            const float* row = ea + (size_t)(e0 + e)*EAC;
            float2 v = *(const float2*)(row + 2*lane);
            sEaF[(2*lane)*66   + 2*pr + par] = v.x;
            sEaF[(2*lane+1)*66 + 2*pr + par] = v.y;
            if (lane == 0) sEaF[64*66 + 2*pr + par] = row[64];
        }
        __syncthreads();

        // GEMM: acc[c][p] = f32x2 accumulator for channel 4*lane+c, edge pair p
        ull a0[4], a1[4], a2[4], a3[4];
        #pragma unroll
        for (int p = 0; p < 4; p++) { a0[p]=bi0; a1[p]=bi1; a2[p]=bi2; a3[p]=bi3; }
        #pragma unroll 5
        for (int d = 0; d < EF; d++) {
            float4 wv = sW4[d*32 + lane];
            ull w0 = dup2(wv.x), w1 = dup2(wv.y), w2 = dup2(wv.z), w3 = dup2(wv.w);
            const ull* er = sEa2 + d*33 + pb;
            #pragma unroll
            for (int p = 0; p < 4; p++) {
                ull ep = er[p];
                fma2(a0[p], ep, w0);
                fma2(a1[p], ep, w1);
                fma2(a2[p], ep, w2);
                fma2(a3[p], ep, w3);
            }
        }
        #pragma unroll 1
        for (int p = 0; p < 4; p++) {
            float2 c0 = unpack2(a0[p]), c1 = unpack2(a1[p]);
            float2 c2 = unpack2(a2[p]), c3 = unpack2(a3[p]);
            #pragma unroll
            for (int par = 0; par < 2; par++) {
                int e  = eb + 2*p + par;
                int s = sIdx[e], t = sIdx[ET + e];
                float v0 = par ? c0.y : c0.x;
                float v1 = par ? c1.y : c1.x;
                float v2 = par ? c2.y : c2.x;
                float v3 = par ? c3.y : c3.x;
                float4 xa = __ldg((const float4*)(g_XA + (size_t)s*C + 4*lane));
                float4 xb = __ldg((const float4*)(g_XB + (size_t)t*C + 4*lane));
                float4 xm = __ldg((const float4*)(g_Xm + (size_t)s*C + 4*lane));
                v0 += xa.x + xb.x;
                v1 += xa.y + xb.y;
                v2 += xa.z + xb.z;
                v3 += xa.w + xb.w;
                v0 = v0 > 0.0f ? v0 : __expf(v0) - 1.0f;
                v1 = v1 > 0.0f ? v1 : __expf(v1) - 1.0f;
                v2 = v2 > 0.0f ? v2 : __expf(v2) - 1.0f;
                v3 = v3 > 0.0f ? v3 : __expf(v3) - 1.0f;
                float msk = (sEaF[2*(pb + p) + par] < 8.0f) ? 1.0f : 0.0f;
                v0 *= msk; v1 *= msk; v2 *= msk; v3 *= msk;
                float pd = v0*xm.x + v1*xm.y + v2*xm.z + v3*xm.w;
                #pragma unroll
                for (int off = 16; off; off >>= 1)
                    pd += __shfl_xor_sync(0xffffffffu, pd, off);
                float av = tanh_fast(pd);
                float sc = __expf(av);
                asm volatile("red.global.add.v4.f32 [%0], {%1, %2, %3, %4};"
                             :: "l"(g_aggr + (size_t)s*C + 4*lane),
                                "f"(sc*v0), "f"(sc*v1), "f"(sc*v2), "f"(sc*v3)
                             : "memory");
                if (lane == 0) atomicAdd(&g_asum[s], av);
            }
        }
    }
}

// ---------------- K4: out = (x + exp(-asum)*aggr) @ Wu + bu ------------------
__global__ __launch_bounds__(256, 2) void node_out_kernel(const float* __restrict__ x,
                                                          const float* __restrict__ Wu,
                                                          const float* __restrict__ bu,
                                                          float* __restrict__ out) {
    extern __shared__ unsigned char smem[];
    float4*     sW4  = (float4*)smem;
    ulonglong2* sWu2 = (ulonglong2*)smem;
    ull*        sX2  = (ull*)(smem + 65536);
    int tid = threadIdx.x, lane = tid & 31, w = tid >> 5;
    const float4* W4 = (const float4*)Wu;
    for (int i = tid; i < C*32; i += 256) sW4[i] = W4[i];
    float4 b4 = *(const float4*)(bu + 4*lane);
    ull bi0 = pack2(b4.x, b4.y), bi1 = pack2(b4.z, b4.w);
    const int ntiles = (NN + 31) / 32;
    for (int tile = blockIdx.x; tile < ntiles; tile += gridDim.x) {
        int n0 = tile * 32;
        __syncthreads();
        for (int i = tid; i < C*32; i += 256) {
            int d = i & 127, n = i >> 7, ng = n0 + n;
            float v = 0.0f;
            if (ng < NN) {
                float dsc = __expf(-g_asum[ng]);
                v = x[(size_t)ng*C + d] + dsc * g_aggr[(size_t)ng*C + d];
            }
            sX2[d*33 + n] = dup2(v);
        }
        __syncthreads();
        int nb = w * 4;
        ull a0[4], a1[4];
        node_gemm_tile(sX2, sWu2, lane, nb, bi0, bi1, a0, a1);
        #pragma unroll 1
        for (int e = 0; e < 4; e++) {
            int n = n0 + nb + e;
            if (n < NN) {
                float2 f0 = unpack2(a0[e]), f1 = unpack2(a1[e]);
                float4 o; o.x = f0.x; o.y = f0.y; o.z = f1.x; o.w = f1.y;
                *(float4*)(out + (size_t)n*C + 4*lane) = o;
            }
        }
    }
}

// ---------------- host launcher ----------------------------------------------
extern "C" void kernel_launch(void* const* d_in, const int* in_sizes, int n_in,
                              void* d_out, int out_size) {
    const float* x   = (const float*)d_in[0];
    const int*   ei  = (const int*  )d_in[1];
    const float* ea  = (const float*)d_in[2];
    const float* Wf  = (const float*)d_in[3];
    const float* bf  = (const float*)d_in[4];
    const float* Wq  = (const float*)d_in[5];
    const float* Wk  = (const float*)d_in[6];
    const float* Wa  = (const float*)d_in[7];
    const float* Wu  = (const float*)d_in[8];
    const float* bu  = (const float*)d_in[9];
    float* out = (float*)d_out;

    (void)in_sizes; (void)n_in; (void)out_size;

    cudaFuncSetAttribute(node_pre_kernel, cudaFuncAttributeMaxDynamicSharedMemorySize, NODE_SMEM);
    cudaFuncSetAttribute(node_out_kernel, cudaFuncAttributeMaxDynamicSharedMemorySize, NODE_SMEM);
    cudaFuncSetAttribute(edge1_kernel,    cudaFuncAttributeMaxDynamicSharedMemorySize, E1_SMEM);

    prep_kernel<<<C, C>>>(Wf, Wq, Wk, Wa);
    zero_kernel<<<(NN*C + 255) / 256, 256>>>();
    node_pre_kernel<<<304, 256, NODE_SMEM>>>(x);
    edge1_kernel<<<608, 256, E1_SMEM>>>(ea, ei, Wf, bf);
    node_out_kernel<<<304, 256, NODE_SMEM>>>(x, Wu, bu, out);
}